// round 5
// baseline (speedup 1.0000x reference)
#include <cuda_runtime.h>
#include <cuda_bf16.h>
#include <cstdint>
#include <math.h>

#define BB 32768
#define DD 256
#define NN 8192
#define CAP 128

// ---------------- scratch (__device__ globals; no allocation allowed) -------
__device__ int8_t g_xq[(size_t)BB * DD];           // int8(x/sx)        8 MB
__device__ int8_t g_eq[(size_t)NN * DD];           // int8(e_hat/se)    2 MB
__device__ float  g_ehat[(size_t)NN * DD];         // e_hat fp32        8 MB
__device__ float  g_se[NN];                        // per-codeword scale
__device__ int    g_cand[(size_t)BB * CAP];        // candidate cols   16 MB
__device__ int    g_ccnt[BB];
__device__ float  g_sx[BB];                        // per-row x scale
__device__ float  g_l1x[BB];                       // per-row ||x||_1
__device__ float  g_commit[BB];
__device__ unsigned g_semax_u;                     // ford(max se)  (idempotent)
__device__ unsigned g_l1emax_u;                    // ford(max ||e_hat||_1)

// ---------------- helpers ---------------------------------------------------
__device__ __forceinline__ unsigned ford(float f) {
    unsigned u = __float_as_uint(f);
    return (u & 0x80000000u) ? ~u : (u | 0x80000000u);
}
__device__ __forceinline__ float unford(unsigned u) {
    unsigned v = (u & 0x80000000u) ? (u & 0x7fffffffu) : ~u;
    return __uint_as_float(v);
}
__device__ __forceinline__ uint32_t s2u(const void* p) {
    uint32_t a;
    asm("{ .reg .u64 t; cvta.to.shared.u64 t, %1; cvt.u32.u64 %0, t; }"
        : "=r"(a) : "l"(p));
    return a;
}
// smem tile: 128 rows x 256 s8 (256 B/row = 16 x 16B units), XOR swizzle
__device__ __forceinline__ uint32_t soff8(int row, int u) {
    return (uint32_t)(row * 256 + ((u ^ (row & 7)) << 4));
}
__device__ __forceinline__ void cpa16(uint32_t s, const void* g) {
    asm volatile("cp.async.cg.shared.global [%0], [%1], 16;" :: "r"(s), "l"(g));
}
#define CPA_COMMIT() asm volatile("cp.async.commit_group;" ::: "memory")
#define CPA_WAIT0()  asm volatile("cp.async.wait_group 0;" ::: "memory")

#define LDSM4(r0, r1, r2, r3, addr) \
    asm volatile("ldmatrix.sync.aligned.m8n8.x4.shared.b16 {%0,%1,%2,%3}, [%4];" \
                 : "=r"(r0), "=r"(r1), "=r"(r2), "=r"(r3) : "r"(addr))

#define IMMA16832(d, a0, a1, a2, a3, b0, b1) \
    asm volatile("mma.sync.aligned.m16n8k32.row.col.s32.s8.s8.s32 " \
                 "{%0,%1,%2,%3}, {%4,%5,%6,%7}, {%8,%9}, {%0,%1,%2,%3};" \
                 : "+r"((d)[0]), "+r"((d)[1]), "+r"((d)[2]), "+r"((d)[3]) \
                 : "r"(a0), "r"(a1), "r"(a2), "r"(a3), "r"(b0), "r"(b1))

__device__ __forceinline__ void append_cand(int row, int col) {
    int p = atomicAdd(&g_ccnt[row], 1);
    if (p < CAP) g_cand[(size_t)row * CAP + p] = col;
}
__device__ __forceinline__ int8_t q8(float v, float inv_s) {
    int q = __float2int_rn(v * inv_s);
    q = max(-127, min(127, q));
    return (int8_t)q;
}

// ---------------- prep kernels ---------------------------------------------
__global__ void prep_x_kernel(const float* __restrict__ x) {
    int w = threadIdx.x >> 5, lane = threadIdx.x & 31;
    int b = blockIdx.x * 8 + w;
    float v[8];
    float mx = 0.f, l1 = 0.f;
#pragma unroll
    for (int j = 0; j < 8; j++) {
        v[j] = x[(size_t)b * DD + j * 32 + lane];
        float a = fabsf(v[j]);
        mx = fmaxf(mx, a);
        l1 += a;
    }
#pragma unroll
    for (int o = 16; o > 0; o >>= 1) {
        mx = fmaxf(mx, __shfl_xor_sync(0xffffffffu, mx, o));
        l1 += __shfl_xor_sync(0xffffffffu, l1, o);
    }
    float sx = fmaxf(mx / 127.0f, 1e-20f);
    float inv = 1.0f / sx;
#pragma unroll
    for (int j = 0; j < 8; j++)
        g_xq[(size_t)b * DD + j * 32 + lane] = q8(v[j], inv);
    if (lane == 0) {
        g_sx[b] = sx;
        g_l1x[b] = l1;
        g_ccnt[b] = 0;                       // re-zero every launch
    }
}

__global__ void prep_e_kernel(const float* __restrict__ e) {
    int w = threadIdx.x >> 5, lane = threadIdx.x & 31;
    int n = blockIdx.x * 8 + w;
    float v[8];
    float ss = 0.f;
#pragma unroll
    for (int j = 0; j < 8; j++) {
        v[j] = e[(size_t)n * DD + j * 32 + lane];
        ss += v[j] * v[j];
    }
#pragma unroll
    for (int o = 16; o > 0; o >>= 1) ss += __shfl_xor_sync(0xffffffffu, ss, o);
    float invn = 1.f / fmaxf(sqrtf(ss), 1e-12f);
    float mx = 0.f, l1 = 0.f;
#pragma unroll
    for (int j = 0; j < 8; j++) {
        v[j] *= invn;
        g_ehat[(size_t)n * DD + j * 32 + lane] = v[j];
        float a = fabsf(v[j]);
        mx = fmaxf(mx, a);
        l1 += a;
    }
#pragma unroll
    for (int o = 16; o > 0; o >>= 1) {
        mx = fmaxf(mx, __shfl_xor_sync(0xffffffffu, mx, o));
        l1 += __shfl_xor_sync(0xffffffffu, l1, o);
    }
    float se = fmaxf(mx / 127.0f, 1e-20f);
    float inv = 1.0f / se;
#pragma unroll
    for (int j = 0; j < 8; j++)
        g_eq[(size_t)n * DD + j * 32 + lane] = q8(v[j], inv);
    if (lane == 0) {
        g_se[n] = se;
        atomicMax(&g_semax_u, ford(se));       // idempotent across replays
        atomicMax(&g_l1emax_u, ford(l1));
    }
}

// ---------------- IMMA s8 GEMM with in-flight candidate capture ------------
// smem: A 32KB | B0 32KB | B1 32KB | sx 512B | rowmax 512B | marg 512B
#define SM_B0 32768
#define SM_B1 65536
#define SM_SX 98304
#define SM_RM 98816
#define SM_MG 99328
#define DYN_SMEM (99328 + 512)

__global__ void __launch_bounds__(256, 2) gemm_kernel() {
    extern __shared__ char sm[];
    uint32_t sA = s2u(sm);
    int tid = threadIdx.x, wid = tid >> 5, lane = tid & 31;
    int rb = blockIdx.x * 128;
    float* sx_s = (float*)(sm + SM_SX);
    unsigned* rowmax_s = (unsigned*)(sm + SM_RM);
    float* marg_s = (float*)(sm + SM_MG);
    if (tid < 128) {
        float sx = g_sx[rb + tid];
        sx_s[tid] = sx;
        rowmax_s[tid] = 0u;                    // == ford(-inf)
        // rigorous worst-case int8 dot error bound + slack
        float semax = unford(g_semax_u);
        float l1emax = unford(g_l1emax_u);
        marg_s[tid] = 0.5f * sx * l1emax + 0.5f * semax * g_l1x[rb + tid] +
                      0.25f * DD * sx * semax + 0.02f;
    }

    // prologue: A tile (rows rb..rb+127, 256B each) + B chunk 0
#pragma unroll
    for (int i = 0; i < 8; i++) {
        int q = tid + (i << 8);
        int row = q >> 4, u = q & 15;
        cpa16(sA + soff8(row, u), g_xq + (size_t)(rb + row) * DD + u * 16);
        cpa16(sA + SM_B0 + soff8(row, u), g_eq + (size_t)row * DD + u * 16);
    }
    CPA_COMMIT();
    CPA_WAIT0();
    __syncthreads();

    int wm = wid >> 2, wn = wid & 3;
    int g = lane >> 2, cpair = (lane & 3) * 2;

    float sxv[8];
#pragma unroll
    for (int s = 0; s < 8; s++)
        sxv[s] = sx_s[wm * 64 + (s >> 1) * 16 + (s & 1) * 8 + g];

    // ldmatrix address components
    int la15 = lane & 15;
    int rowA_c = wm * 64 + la15;               // + mi*16
    int uA_c = (lane >> 4);                    // + ks*2
    int rowB_c = wn * 32 + ((lane >> 4) & 1) * 8 + (lane & 7);  // + pair*16
    int uB_c = (lane >> 3) & 1;                // + ks*2

    for (int t = 0; t < 64; t++) {
        uint32_t sBc = sA + ((t & 1) ? SM_B1 : SM_B0);

        // prefetch per-column scales for this tile (L2-hot)
        float se8[8];
#pragma unroll
        for (int ni = 0; ni < 4; ni++) {
            int c = t * 128 + wn * 32 + ni * 8 + cpair;
            se8[ni * 2] = g_se[c];
            se8[ni * 2 + 1] = g_se[c + 1];
        }

        if (t < 63) {
            uint32_t sBn = sA + ((t & 1) ? SM_B0 : SM_B1);
            const int8_t* gsrc = g_eq + (size_t)(t + 1) * 128 * DD;
#pragma unroll
            for (int i = 0; i < 8; i++) {
                int q = tid + (i << 8);
                int row = q >> 4, u = q & 15;
                cpa16(sBn + soff8(row, u), gsrc + (size_t)row * DD + u * 16);
            }
            CPA_COMMIT();
        }

        int acc[4][4][4];
#pragma unroll
        for (int mi = 0; mi < 4; mi++)
#pragma unroll
            for (int ni = 0; ni < 4; ni++)
#pragma unroll
                for (int r = 0; r < 4; r++) acc[mi][ni][r] = 0;

#pragma unroll
        for (int ks = 0; ks < 8; ks++) {
            int ub = ks * 2;
            uint32_t b[4][2];
#pragma unroll
            for (int pair = 0; pair < 2; pair++) {
                uint32_t addr = sBc + soff8(rowB_c + pair * 16, ub + uB_c);
                LDSM4(b[pair * 2][0], b[pair * 2][1],
                      b[pair * 2 + 1][0], b[pair * 2 + 1][1], addr);
            }
#pragma unroll
            for (int mi = 0; mi < 4; mi++) {
                uint32_t addr = sA + soff8(rowA_c + mi * 16, ub + uA_c);
                uint32_t a0, a1, a2, a3;
                LDSM4(a0, a1, a2, a3, addr);
#pragma unroll
                for (int ni = 0; ni < 4; ni++)
                    IMMA16832(acc[mi][ni], a0, a1, a2, a3, b[ni][0], b[ni][1]);
            }
        }

        // ---- phase A: per-row tile max of noisy floats -> smem rowmax ------
        float rmloc[8];
#pragma unroll
        for (int mi = 0; mi < 4; mi++) {
            float m0 = -3.4e38f, m1 = -3.4e38f;
            float s0 = sxv[mi * 2], s1 = sxv[mi * 2 + 1];
#pragma unroll
            for (int ni = 0; ni < 4; ni++) {
                float c0 = s0 * se8[ni * 2], c1 = s0 * se8[ni * 2 + 1];
                float c2 = s1 * se8[ni * 2], c3 = s1 * se8[ni * 2 + 1];
                m0 = fmaxf(m0, fmaxf((float)acc[mi][ni][0] * c0,
                                     (float)acc[mi][ni][1] * c1));
                m1 = fmaxf(m1, fmaxf((float)acc[mi][ni][2] * c2,
                                     (float)acc[mi][ni][3] * c3));
            }
            rmloc[mi * 2] = m0;
            rmloc[mi * 2 + 1] = m1;
        }
#pragma unroll
        for (int s = 0; s < 8; s++) {
            float m = rmloc[s];
            m = fmaxf(m, __shfl_xor_sync(0xffffffffu, m, 1));
            m = fmaxf(m, __shfl_xor_sync(0xffffffffu, m, 2));
            rmloc[s] = m;                       // quad max (lanes share rows)
        }
        if ((lane & 3) == 0) {
#pragma unroll
            for (int s = 0; s < 8; s++) {
                int rl = wm * 64 + (s >> 1) * 16 + (s & 1) * 8 + g;
                atomicMax(&rowmax_s[rl], ford(rmloc[s]));
            }
        }
        if (t < 63) CPA_WAIT0();
        __syncthreads();   // rowmax visible; B prefetch landed

        // ---- phase B: append candidates above (rowmax - margin) ------------
        int ncol = t * 128 + wn * 32 + cpair;
#pragma unroll
        for (int mi = 0; mi < 4; mi++) {
#pragma unroll
            for (int half = 0; half < 2; half++) {
                int rl = wm * 64 + mi * 16 + half * 8 + g;
                float qm = rmloc[mi * 2 + half];
                float thr = unford(rowmax_s[rl]) - marg_s[rl];
                if (qm > thr) {
                    float sr = sxv[mi * 2 + half];
#pragma unroll
                    for (int ni = 0; ni < 4; ni++) {
                        float v0 = (float)acc[mi][ni][half * 2] * sr * se8[ni * 2];
                        float v1 = (float)acc[mi][ni][half * 2 + 1] * sr *
                                   se8[ni * 2 + 1];
                        if (v0 > thr) append_cand(rb + rl, ncol + ni * 8);
                        if (v1 > thr) append_cand(rb + rl, ncol + ni * 8 + 1);
                    }
                }
            }
        }
    }
}

// ---------------- exact fp32 rescore + fused epilogue ----------------------
__global__ void __launch_bounds__(256) rescore_kernel(const float* __restrict__ x,
                                                      const float* __restrict__ e,
                                                      float* __restrict__ out) {
    __shared__ float xs[256];
    __shared__ float wbv[8];
    __shared__ int wbi[8];
    __shared__ int idx_s;
    int b = blockIdx.x, t = threadIdx.x, w = t >> 5, lane = t & 31;

    xs[t] = x[(size_t)b * DD + t];
    __syncthreads();

    int c = g_ccnt[b];
    float bestv = -3.4e38f;
    int bestn = NN;
    const float4* xv4 = (const float4*)&xs[lane * 8];
    float4 x0 = xv4[0], x1 = xv4[1];

    if (c <= CAP) {
        for (int i = w; i < c; i += 8) {
            int n = g_cand[(size_t)b * CAP + i];
            const float4* ep = (const float4*)(g_ehat + (size_t)n * DD);
            float4 e0 = ep[lane * 2], e1 = ep[lane * 2 + 1];
            float p = x0.x * e0.x + x0.y * e0.y + x0.z * e0.z + x0.w * e0.w +
                      x1.x * e1.x + x1.y * e1.y + x1.z * e1.z + x1.w * e1.w;
#pragma unroll
            for (int o = 16; o > 0; o >>= 1)
                p += __shfl_xor_sync(0xffffffffu, p, o);
            if (p > bestv || (p == bestv && n < bestn)) { bestv = p; bestn = n; }
        }
    } else {
        // overflow fallback (provably correct, ~never taken): full fp32 row
        for (int n = w * (NN / 8); n < (w + 1) * (NN / 8); n++) {
            const float4* ep = (const float4*)(g_ehat + (size_t)n * DD);
            float4 e0 = ep[lane * 2], e1 = ep[lane * 2 + 1];
            float p = x0.x * e0.x + x0.y * e0.y + x0.z * e0.z + x0.w * e0.w +
                      x1.x * e1.x + x1.y * e1.y + x1.z * e1.z + x1.w * e1.w;
#pragma unroll
            for (int o = 16; o > 0; o >>= 1)
                p += __shfl_xor_sync(0xffffffffu, p, o);
            if (p > bestv || (p == bestv && n < bestn)) { bestv = p; bestn = n; }
        }
    }
    if (lane == 0) { wbv[w] = bestv; wbi[w] = bestn; }
    __syncthreads();
    if (t == 0) {
        float bv = -3.4e38f; int bi = NN;
#pragma unroll
        for (int i = 0; i < 8; i++) {
            if (wbv[i] > bv || (wbv[i] == bv && wbi[i] < bi)) {
                bv = wbv[i]; bi = wbi[i];
            }
        }
        idx_s = (bi == NN) ? 0 : bi;
    }
    __syncthreads();
    int idx = idx_s;

    // fused epilogue (same math as rounds 1/3/4)
    float xvv = xs[t];
    float cv = e[(size_t)idx * DD + t];
    float s1 = xvv * cv, s2 = cv * cv, s3 = xvv * xvv;
#pragma unroll
    for (int o = 16; o > 0; o >>= 1) {
        s1 += __shfl_xor_sync(0xffffffffu, s1, o);
        s2 += __shfl_xor_sync(0xffffffffu, s2, o);
        s3 += __shfl_xor_sync(0xffffffffu, s3, o);
    }
    __shared__ float r1[8], r2[8], r3[8];
    __shared__ float bc[3];
    if (lane == 0) { r1[w] = s1; r2[w] = s2; r3[w] = s3; }
    __syncthreads();
    if (t == 0) {
        float d = 0.f, cc = 0.f, xx = 0.f;
#pragma unroll
        for (int i = 0; i < 8; i++) { d += r1[i]; cc += r2[i]; xx += r3[i]; }
        bc[0] = d; bc[1] = cc; bc[2] = xx;
    }
    __syncthreads();
    float dot = bc[0], csq = bc[1], xsq = bc[2];
    float scalar = dot / (csq + 1e-8f);
    float proj = scalar * cv;
    out[(size_t)b * DD + t] = xvv + (proj - xvv);
    if (t == 0) {
        float pn = fabsf(scalar) * sqrtf(csq);
        float commit = (scalar * dot) /
                       (fmaxf(pn, 1e-8f) * fmaxf(sqrtf(xsq), 1e-8f));
        g_commit[b] = 1.0f - commit;
        out[(size_t)BB * DD + 1 + b] = (float)idx;
        out[(size_t)BB * DD + 1 + BB + b] = scalar;
    }
}

// ---------------- loss -----------------------------------------------------
__global__ void loss_kernel(float* __restrict__ out) {
    __shared__ float sh[256];
    float s = 0.f;
    for (int i = threadIdx.x; i < BB; i += 256) s += g_commit[i];
    sh[threadIdx.x] = s;
    __syncthreads();
    for (int o = 128; o > 0; o >>= 1) {
        if (threadIdx.x < o) sh[threadIdx.x] += sh[threadIdx.x + o];
        __syncthreads();
    }
    if (threadIdx.x == 0) out[(size_t)BB * DD] = 0.25f * sh[0] / (float)BB;
}

// ---------------------------------------------------------------------------
extern "C" void kernel_launch(void* const* d_in, const int* in_sizes, int n_in,
                              void* d_out, int out_size) {
    const float* x = (const float*)d_in[0];
    const float* e = (const float*)d_in[1];
    float* out = (float*)d_out;

    cudaFuncSetAttribute(gemm_kernel,
                         cudaFuncAttributeMaxDynamicSharedMemorySize, DYN_SMEM);
    prep_e_kernel<<<NN / 8, 256>>>(e);
    prep_x_kernel<<<BB / 8, 256>>>(x);
    gemm_kernel<<<BB / 128, 256, DYN_SMEM>>>();
    rescore_kernel<<<BB, 256>>>(x, e, out);
    loss_kernel<<<1, 256>>>(out);
}

// round 6
// speedup vs baseline: 2.1561x; 2.1561x over previous
#include <cuda_runtime.h>
#include <cuda_bf16.h>
#include <cstdint>
#include <math.h>

#define BB 32768
#define DD 256
#define NN 8192
#define RCAP 64

// ---------------- scratch (__device__ globals; no allocation allowed) -------
__device__ __nv_bfloat16 g_xb[(size_t)BB * DD];    // bf16(x)          16 MB
__device__ __nv_bfloat16 g_eb[(size_t)NN * DD];    // bf16(e_hat)       4 MB
__device__ float         g_ehat[(size_t)NN * DD];  // e_hat fp32        8 MB
__device__ float g_xnorm[BB];
__device__ float g_commit[BB];

// ---------------- helpers ---------------------------------------------------
__device__ __forceinline__ unsigned ford(float f) {
    unsigned u = __float_as_uint(f);
    return (u & 0x80000000u) ? ~u : (u | 0x80000000u);
}
__device__ __forceinline__ float unford(unsigned u) {
    unsigned v = (u & 0x80000000u) ? (u & 0x7fffffffu) : ~u;
    return __uint_as_float(v);
}
__device__ __forceinline__ uint32_t s2u(const void* p) {
    uint32_t a;
    asm("{ .reg .u64 t; cvta.to.shared.u64 t, %1; cvt.u32.u64 %0, t; }"
        : "=r"(a) : "l"(p));
    return a;
}
// smem tile layout: 128 rows x 256 bf16 (512 B/row), 16B units XOR-swizzled
__device__ __forceinline__ uint32_t soff(int row, int u) {
    return (uint32_t)(row * 512 + ((u ^ (row & 7)) << 4));
}
__device__ __forceinline__ void cpa16(uint32_t s, const void* g) {
    asm volatile("cp.async.cg.shared.global [%0], [%1], 16;" :: "r"(s), "l"(g));
}
#define CPA_COMMIT() asm volatile("cp.async.commit_group;" ::: "memory")
#define CPA_WAIT0()  asm volatile("cp.async.wait_group 0;" ::: "memory")

#define LDSM4(r0, r1, r2, r3, addr) \
    asm volatile("ldmatrix.sync.aligned.m8n8.x4.shared.b16 {%0,%1,%2,%3}, [%4];" \
                 : "=r"(r0), "=r"(r1), "=r"(r2), "=r"(r3) : "r"(addr))

#define MMA16816(d, a0, a1, a2, a3, b0, b1) \
    asm volatile("mma.sync.aligned.m16n8k16.row.col.f32.bf16.bf16.f32 " \
                 "{%0,%1,%2,%3}, {%4,%5,%6,%7}, {%8,%9}, {%0,%1,%2,%3};" \
                 : "+f"((d)[0]), "+f"((d)[1]), "+f"((d)[2]), "+f"((d)[3]) \
                 : "r"(a0), "r"(a1), "r"(a2), "r"(a3), "r"(b0), "r"(b1))

// ---------------- prep kernels ---------------------------------------------
__global__ void prep_x_kernel(const float* __restrict__ x) {
    int w = threadIdx.x >> 5, lane = threadIdx.x & 31;
    int b = blockIdx.x * 8 + w;
    float ss = 0.f;
#pragma unroll
    for (int j = 0; j < 8; j++) {
        float v = x[(size_t)b * DD + j * 32 + lane];
        ss += v * v;
        g_xb[(size_t)b * DD + j * 32 + lane] = __float2bfloat16(v);
    }
#pragma unroll
    for (int o = 16; o > 0; o >>= 1) ss += __shfl_xor_sync(0xffffffffu, ss, o);
    if (lane == 0) g_xnorm[b] = sqrtf(ss);
}

__global__ void prep_e_kernel(const float* __restrict__ e) {
    int w = threadIdx.x >> 5, lane = threadIdx.x & 31;
    int n = blockIdx.x * 8 + w;
    float v[8];
    float ss = 0.f;
#pragma unroll
    for (int j = 0; j < 8; j++) {
        v[j] = e[(size_t)n * DD + j * 32 + lane];
        ss += v[j] * v[j];
    }
#pragma unroll
    for (int o = 16; o > 0; o >>= 1) ss += __shfl_xor_sync(0xffffffffu, ss, o);
    float inv = 1.f / fmaxf(sqrtf(ss), 1e-12f);
#pragma unroll
    for (int j = 0; j < 8; j++) {
        float h = v[j] * inv;
        g_ehat[(size_t)n * DD + j * 32 + lane] = h;
        g_eb[(size_t)n * DD + j * 32 + lane] = __float2bfloat16(h);
    }
}

// ---- fused HMMA bf16 GEMM + candidate capture + rescore + epilogue --------
// smem: A 64KB | B0 64KB | B1 64KB | rowmax 512 | marg 512 | cnt 512 |
//       bestn 512 | lists 32KB  => 231424 B dynamic
#define SM_B0 65536
#define SM_B1 131072
#define SM_RM 196608
#define SM_MG 197120
#define SM_CC 197632
#define SM_BI 198144
#define SM_CL 198656
#define DYN_SMEM (198656 + RCAP * 128 * 4)

__global__ void __launch_bounds__(256) gemm_kernel(const float* __restrict__ x,
                                                   const float* __restrict__ e,
                                                   float* __restrict__ out) {
    extern __shared__ char sm[];
    uint32_t sA = s2u(sm);
    int tid = threadIdx.x, wid = tid >> 5, lane = tid & 31;
    int rb = blockIdx.x * 128;
    unsigned* rowmax_s = (unsigned*)(sm + SM_RM);
    float* marg_s = (float*)(sm + SM_MG);
    int* cnt_s = (int*)(sm + SM_CC);
    int* bestn_s = (int*)(sm + SM_BI);
    int* list_s = (int*)(sm + SM_CL);
    if (tid < 128) {
        rowmax_s[tid] = ford(-3.4e38f);
        cnt_s[tid] = 0;
        // bound on bf16-input dot error (~0.004*||x||) with >2x slack
        marg_s[tid] = 0.01f * g_xnorm[rb + tid] + 0.02f;
    }

    // prologue: A tile (rows rb..rb+127) + B chunk 0
#pragma unroll
    for (int i = 0; i < 16; i++) {
        int q = tid + (i << 8);
        int row = q >> 5, u = q & 31;
        cpa16(sA + soff(row, u), g_xb + (size_t)(rb + row) * DD + u * 8);
        cpa16(sA + SM_B0 + soff(row, u), g_eb + (size_t)row * DD + u * 8);
    }
    CPA_COMMIT();
    CPA_WAIT0();
    __syncthreads();

    int wm = wid >> 2, wn = wid & 3;
    int g = lane >> 2, cpair = (lane & 3) * 2;

    // per-lane ldmatrix row/ku components
    int la7 = lane & 7;
    int rowA_c = wm * 64 + la7 + ((lane >> 3) & 1) * 8;  // + mi*16
    int kuA_c = (lane >> 4);
    int rowB_c = wn * 32 + la7 + ((lane >> 4) & 1) * 8;  // + h*16
    int kuB_c = (lane >> 3) & 1;

    for (int t = 0; t < 64; t++) {
        uint32_t sBc = sA + ((t & 1) ? SM_B1 : SM_B0);
        if (t < 63) {
            uint32_t sBn = sA + ((t & 1) ? SM_B0 : SM_B1);
            const __nv_bfloat16* gsrc = g_eb + (size_t)(t + 1) * 128 * DD;
#pragma unroll
            for (int i = 0; i < 16; i++) {
                int q = tid + (i << 8);
                int row = q >> 5, u = q & 31;
                cpa16(sBn + soff(row, u), gsrc + (size_t)row * DD + u * 8);
            }
            CPA_COMMIT();
        }

        float acc[4][4][4];
#pragma unroll
        for (int mi = 0; mi < 4; mi++)
#pragma unroll
            for (int ni = 0; ni < 4; ni++)
#pragma unroll
                for (int r = 0; r < 4; r++) acc[mi][ni][r] = 0.f;

#pragma unroll
        for (int ks = 0; ks < 16; ks++) {
            int kb = ks * 2;
            uint32_t b[4][2];
#pragma unroll
            for (int h = 0; h < 2; h++) {
                int rowB = rowB_c + h * 16;
                uint32_t addr = sBc + soff(rowB, kb + kuB_c);
                LDSM4(b[h * 2][0], b[h * 2][1], b[h * 2 + 1][0], b[h * 2 + 1][1],
                      addr);
            }
#pragma unroll
            for (int mi = 0; mi < 4; mi++) {
                int rowA = rowA_c + mi * 16;
                uint32_t addr = sA + soff(rowA, kb + kuA_c);
                uint32_t a0, a1, a2, a3;
                LDSM4(a0, a1, a2, a3, addr);
#pragma unroll
                for (int ni = 0; ni < 4; ni++)
                    MMA16816(acc[mi][ni], a0, a1, a2, a3, b[ni][0], b[ni][1]);
            }
        }

        // ---- phase A: per-row tile max -> smem rowmax (quad pre-reduced) ----
        float rmloc[8];
#pragma unroll
        for (int mi = 0; mi < 4; mi++) {
            float m0 = -3.4e38f, m1 = -3.4e38f;
#pragma unroll
            for (int ni = 0; ni < 4; ni++) {
                m0 = fmaxf(m0, fmaxf(acc[mi][ni][0], acc[mi][ni][1]));
                m1 = fmaxf(m1, fmaxf(acc[mi][ni][2], acc[mi][ni][3]));
            }
            rmloc[mi * 2] = m0;
            rmloc[mi * 2 + 1] = m1;
        }
#pragma unroll
        for (int s = 0; s < 8; s++) {
            float m = rmloc[s];
            m = fmaxf(m, __shfl_xor_sync(0xffffffffu, m, 1));
            m = fmaxf(m, __shfl_xor_sync(0xffffffffu, m, 2));
            rmloc[s] = m;                       // quad max (lanes share rows)
        }
        if ((lane & 3) == 0) {
#pragma unroll
            for (int s = 0; s < 8; s++) {
                int rl = wm * 64 + (s >> 1) * 16 + (s & 1) * 8 + g;
                atomicMax(&rowmax_s[rl], ford(rmloc[s]));
            }
        }
        if (t < 63) CPA_WAIT0();
        __syncthreads();   // rowmax visible to all; B prefetch landed

        // ---- phase B: append candidates above (rowmax - margin) ------------
        int ncol = t * 128 + wn * 32 + cpair;
#pragma unroll
        for (int mi = 0; mi < 4; mi++) {
#pragma unroll
            for (int half = 0; half < 2; half++) {
                int rl = wm * 64 + mi * 16 + half * 8 + g;
                float qm = rmloc[mi * 2 + half];
                float thr = unford(rowmax_s[rl]) - marg_s[rl];
                if (qm > thr) {
#pragma unroll
                    for (int ni = 0; ni < 4; ni++) {
                        float v0 = acc[mi][ni][half * 2];
                        float v1 = acc[mi][ni][half * 2 + 1];
                        if (v0 > thr) {
                            int p = atomicAdd(&cnt_s[rl], 1);
                            if (p < RCAP) list_s[rl * RCAP + p] = ncol + ni * 8;
                        }
                        if (v1 > thr) {
                            int p = atomicAdd(&cnt_s[rl], 1);
                            if (p < RCAP) list_s[rl * RCAP + p] = ncol + ni * 8 + 1;
                        }
                    }
                }
            }
        }
    }
    __syncthreads();   // lists complete

    // ---- tail 1: exact fp32 rescore (one warp per row, 16 rows/warp) -------
    for (int rr = wid; rr < 128; rr += 8) {
        int row = rb + rr;
        const float4* xp = (const float4*)(x + (size_t)row * DD);
        float4 xa = xp[lane * 2], xb2 = xp[lane * 2 + 1];
        float bestv = -3.4e38f;
        int bestn = 0;
        int c = cnt_s[rr];
        if (c <= RCAP) {
            for (int i = 0; i < c; i++) {
                int n = list_s[rr * RCAP + i];
                const float4* ep = (const float4*)(g_ehat + (size_t)n * DD);
                float4 e0 = ep[lane * 2], e1 = ep[lane * 2 + 1];
                float p = xa.x * e0.x + xa.y * e0.y + xa.z * e0.z + xa.w * e0.w +
                          xb2.x * e1.x + xb2.y * e1.y + xb2.z * e1.z +
                          xb2.w * e1.w;
#pragma unroll
                for (int o = 16; o > 0; o >>= 1)
                    p += __shfl_xor_sync(0xffffffffu, p, o);
                if (p > bestv || (p == bestv && n < bestn)) { bestv = p; bestn = n; }
            }
        } else {
            // overflow fallback (provably correct, ~never taken): full scan
            for (int n = 0; n < NN; n++) {
                const float4* ep = (const float4*)(g_ehat + (size_t)n * DD);
                float4 e0 = ep[lane * 2], e1 = ep[lane * 2 + 1];
                float p = xa.x * e0.x + xa.y * e0.y + xa.z * e0.z + xa.w * e0.w +
                          xb2.x * e1.x + xb2.y * e1.y + xb2.z * e1.z +
                          xb2.w * e1.w;
#pragma unroll
                for (int o = 16; o > 0; o >>= 1)
                    p += __shfl_xor_sync(0xffffffffu, p, o);
                if (p > bestv || (p == bestv && n < bestn)) { bestv = p; bestn = n; }
            }
        }
        if (lane == 0) bestn_s[rr] = bestn;
    }
    __syncthreads();

    // ---- tail 2: projection / x_q / commit epilogue (warp per row) ---------
    for (int rr = wid; rr < 128; rr += 8) {
        int row = rb + rr;
        int idx = bestn_s[rr];
        const float4* xp = (const float4*)(x + (size_t)row * DD);
        const float4* ep = (const float4*)(e + (size_t)idx * DD);
        float4 xa = xp[lane * 2], xb2 = xp[lane * 2 + 1];
        float4 ea = ep[lane * 2], eb2 = ep[lane * 2 + 1];
        float s1 = xa.x * ea.x + xa.y * ea.y + xa.z * ea.z + xa.w * ea.w +
                   xb2.x * eb2.x + xb2.y * eb2.y + xb2.z * eb2.z + xb2.w * eb2.w;
        float s2 = ea.x * ea.x + ea.y * ea.y + ea.z * ea.z + ea.w * ea.w +
                   eb2.x * eb2.x + eb2.y * eb2.y + eb2.z * eb2.z + eb2.w * eb2.w;
        float s3 = xa.x * xa.x + xa.y * xa.y + xa.z * xa.z + xa.w * xa.w +
                   xb2.x * xb2.x + xb2.y * xb2.y + xb2.z * xb2.z + xb2.w * xb2.w;
#pragma unroll
        for (int o = 16; o > 0; o >>= 1) {
            s1 += __shfl_xor_sync(0xffffffffu, s1, o);
            s2 += __shfl_xor_sync(0xffffffffu, s2, o);
            s3 += __shfl_xor_sync(0xffffffffu, s3, o);
        }
        float dot = s1, csq = s2, xsq = s3;
        float scalar = dot / (csq + 1e-8f);
        float4 o0, o1;
        o0.x = xa.x + (scalar * ea.x - xa.x);
        o0.y = xa.y + (scalar * ea.y - xa.y);
        o0.z = xa.z + (scalar * ea.z - xa.z);
        o0.w = xa.w + (scalar * ea.w - xa.w);
        o1.x = xb2.x + (scalar * eb2.x - xb2.x);
        o1.y = xb2.y + (scalar * eb2.y - xb2.y);
        o1.z = xb2.z + (scalar * eb2.z - xb2.z);
        o1.w = xb2.w + (scalar * eb2.w - xb2.w);
        float4* op = (float4*)(out + (size_t)row * DD);
        op[lane * 2] = o0;
        op[lane * 2 + 1] = o1;
        if (lane == 0) {
            float pn = fabsf(scalar) * sqrtf(csq);
            float commit = (scalar * dot) /
                           (fmaxf(pn, 1e-8f) * fmaxf(sqrtf(xsq), 1e-8f));
            g_commit[row] = 1.0f - commit;
            out[(size_t)BB * DD + 1 + row] = (float)idx;
            out[(size_t)BB * DD + 1 + BB + row] = scalar;
        }
    }
}

// ---------------- loss -----------------------------------------------------
__global__ void loss_kernel(float* __restrict__ out) {
    __shared__ float sh[256];
    float s = 0.f;
    for (int i = threadIdx.x; i < BB; i += 256) s += g_commit[i];
    sh[threadIdx.x] = s;
    __syncthreads();
    for (int o = 128; o > 0; o >>= 1) {
        if (threadIdx.x < o) sh[threadIdx.x] += sh[threadIdx.x + o];
        __syncthreads();
    }
    if (threadIdx.x == 0) out[(size_t)BB * DD] = 0.25f * sh[0] / (float)BB;
}

// ---------------------------------------------------------------------------
extern "C" void kernel_launch(void* const* d_in, const int* in_sizes, int n_in,
                              void* d_out, int out_size) {
    const float* x = (const float*)d_in[0];
    const float* e = (const float*)d_in[1];
    float* out = (float*)d_out;

    cudaFuncSetAttribute(gemm_kernel,
                         cudaFuncAttributeMaxDynamicSharedMemorySize, DYN_SMEM);
    prep_e_kernel<<<NN / 8, 256>>>(e);
    prep_x_kernel<<<BB / 8, 256>>>(x);
    gemm_kernel<<<BB / 128, 256, DYN_SMEM>>>(x, e, out);
    loss_kernel<<<1, 256>>>(out);
}

// round 7
// speedup vs baseline: 2.1682x; 1.0056x over previous
#include <cuda_runtime.h>
#include <cuda_bf16.h>
#include <cstdint>
#include <math.h>

#define BB 32768
#define DD 256
#define NN 8192
#define RT 64          // rows per CTA tile
#define CT 64          // cols per B chunk
#define RCAP 60

// ---------------- scratch (__device__ globals; no allocation allowed) -------
__device__ __nv_bfloat16 g_eb[(size_t)NN * DD];    // bf16(e_hat)       4 MB
__device__ float         g_ehat[(size_t)NN * DD];  // e_hat fp32        8 MB
__device__ float g_commit[BB];
__device__ float g_part[256];

// ---------------- helpers ---------------------------------------------------
__device__ __forceinline__ unsigned ford(float f) {
    unsigned u = __float_as_uint(f);
    return (u & 0x80000000u) ? ~u : (u | 0x80000000u);
}
__device__ __forceinline__ float unford(unsigned u) {
    unsigned v = (u & 0x80000000u) ? (u & 0x7fffffffu) : ~u;
    return __uint_as_float(v);
}
__device__ __forceinline__ uint32_t s2u(const void* p) {
    uint32_t a;
    asm("{ .reg .u64 t; cvta.to.shared.u64 t, %1; cvt.u32.u64 %0, t; }"
        : "=r"(a) : "l"(p));
    return a;
}
// smem tile layout: rows x 256 bf16 (512 B/row), 16B units XOR-swizzled
__device__ __forceinline__ uint32_t soff(int row, int u) {
    return (uint32_t)(row * 512 + ((u ^ (row & 7)) << 4));
}
__device__ __forceinline__ void cpa16(uint32_t s, const void* g) {
    asm volatile("cp.async.cg.shared.global [%0], [%1], 16;" :: "r"(s), "l"(g));
}
#define CPA_COMMIT() asm volatile("cp.async.commit_group;" ::: "memory")
#define CPA_WAIT0()  asm volatile("cp.async.wait_group 0;" ::: "memory")

#define LDSM4(r0, r1, r2, r3, addr) \
    asm volatile("ldmatrix.sync.aligned.m8n8.x4.shared.b16 {%0,%1,%2,%3}, [%4];" \
                 : "=r"(r0), "=r"(r1), "=r"(r2), "=r"(r3) : "r"(addr))

#define MMA16816(d, a0, a1, a2, a3, b0, b1) \
    asm volatile("mma.sync.aligned.m16n8k16.row.col.f32.bf16.bf16.f32 " \
                 "{%0,%1,%2,%3}, {%4,%5,%6,%7}, {%8,%9}, {%0,%1,%2,%3};" \
                 : "+f"((d)[0]), "+f"((d)[1]), "+f"((d)[2]), "+f"((d)[3]) \
                 : "r"(a0), "r"(a1), "r"(a2), "r"(a3), "r"(b0), "r"(b1))

// ---------------- prep: normalize embedding --------------------------------
__global__ void prep_e_kernel(const float* __restrict__ e) {
    int w = threadIdx.x >> 5, lane = threadIdx.x & 31;
    int n = blockIdx.x * 8 + w;
    float v[8];
    float ss = 0.f;
#pragma unroll
    for (int j = 0; j < 8; j++) {
        v[j] = e[(size_t)n * DD + j * 32 + lane];
        ss += v[j] * v[j];
    }
#pragma unroll
    for (int o = 16; o > 0; o >>= 1) ss += __shfl_xor_sync(0xffffffffu, ss, o);
    float inv = 1.f / fmaxf(sqrtf(ss), 1e-12f);
#pragma unroll
    for (int j = 0; j < 8; j++) {
        float h = v[j] * inv;
        g_ehat[(size_t)n * DD + j * 32 + lane] = h;
        g_eb[(size_t)n * DD + j * 32 + lane] = __float2bfloat16(h);
    }
}

// ---- fused HMMA bf16 GEMM + candidate capture + rescore + epilogue --------
// smem: A 32KB | B0 32KB | B1 32KB | rowmax 256 | marg 256 | cnt 256 |
//       besti 256 | lists 15360  => 114688 B -> 2 CTAs/SM
#define SM_B0 32768
#define SM_B1 65536
#define SM_RM 98304
#define SM_MG 98560
#define SM_CC 98816
#define SM_BI 99072
#define SM_CL 99328
#define DYN_SMEM (99328 + RCAP * RT * 4)

__global__ void __launch_bounds__(256, 2) gemm_kernel(const float* __restrict__ x,
                                                      const float* __restrict__ e,
                                                      float* __restrict__ out) {
    extern __shared__ char sm[];
    uint32_t sA = s2u(sm);
    int tid = threadIdx.x, wid = tid >> 5, lane = tid & 31;
    int rb = blockIdx.x * RT;
    unsigned* rowmax_s = (unsigned*)(sm + SM_RM);
    float* marg_s = (float*)(sm + SM_MG);
    int* cnt_s = (int*)(sm + SM_CC);
    int* bestn_s = (int*)(sm + SM_BI);
    int* list_s = (int*)(sm + SM_CL);

    // -- prologue: B chunk 0 via cp.async; A tile fp32->bf16 in-CTA ----------
#pragma unroll
    for (int i = 0; i < 8; i++) {
        int q = tid + (i << 8);
        int row = q >> 5, u = q & 31;
        cpa16(sA + SM_B0 + soff(row, u), g_eb + (size_t)row * DD + u * 8);
    }
    CPA_COMMIT();

    {
        int row = tid >> 2, qq = tid & 3;      // 4 threads per row
        const float4* xp =
            (const float4*)(x + (size_t)(rb + row) * DD + qq * 64);
        float ss = 0.f;
#pragma unroll
        for (int j = 0; j < 8; j++) {
            float4 v0 = xp[2 * j], v1 = xp[2 * j + 1];
            ss += v0.x * v0.x + v0.y * v0.y + v0.z * v0.z + v0.w * v0.w +
                  v1.x * v1.x + v1.y * v1.y + v1.z * v1.z + v1.w * v1.w;
            uint4 st;
            __nv_bfloat162 h;
            h = __floats2bfloat162_rn(v0.x, v0.y); st.x = *(uint32_t*)&h;
            h = __floats2bfloat162_rn(v0.z, v0.w); st.y = *(uint32_t*)&h;
            h = __floats2bfloat162_rn(v1.x, v1.y); st.z = *(uint32_t*)&h;
            h = __floats2bfloat162_rn(v1.z, v1.w); st.w = *(uint32_t*)&h;
            *(uint4*)(sm + soff(row, qq * 8 + j)) = st;
        }
        ss += __shfl_xor_sync(0xffffffffu, ss, 1);
        ss += __shfl_xor_sync(0xffffffffu, ss, 2);
        if (qq == 0) {
            // bound on bf16-input dot error (~0.004*||x||) with >2x slack
            marg_s[row] = 0.01f * sqrtf(ss) + 0.02f;
            rowmax_s[row] = ford(-3.4e38f);
            cnt_s[row] = 0;
        }
    }
    CPA_WAIT0();
    __syncthreads();

    int wm = wid >> 1, wn = wid & 1;           // 4 row-groups x 2 col-groups
    int g = lane >> 2, cpair = (lane & 3) * 2;

    // per-lane ldmatrix row/ku components
    int la7 = lane & 7;
    int rowA = wm * 16 + la7 + ((lane >> 3) & 1) * 8;
    int kuA_c = (lane >> 4);
    int rowB_c = wn * 32 + la7 + ((lane >> 4) & 1) * 8;  // + h*16
    int kuB_c = (lane >> 3) & 1;
    int r0 = wm * 16 + g, r1 = r0 + 8;

    for (int t = 0; t < NN / CT; t++) {
        uint32_t sBc = sA + ((t & 1) ? SM_B1 : SM_B0);
        if (t < NN / CT - 1) {
            uint32_t sBn = sA + ((t & 1) ? SM_B0 : SM_B1);
            const __nv_bfloat16* gsrc = g_eb + (size_t)(t + 1) * CT * DD;
#pragma unroll
            for (int i = 0; i < 8; i++) {
                int q = tid + (i << 8);
                int row = q >> 5, u = q & 31;
                cpa16(sBn + soff(row, u), gsrc + (size_t)row * DD + u * 8);
            }
            CPA_COMMIT();
        }

        float acc[4][4];
#pragma unroll
        for (int ni = 0; ni < 4; ni++)
#pragma unroll
            for (int r = 0; r < 4; r++) acc[ni][r] = 0.f;

#pragma unroll
        for (int ks = 0; ks < 16; ks++) {
            int kb = ks * 2;
            uint32_t b[4][2];
#pragma unroll
            for (int h = 0; h < 2; h++) {
                uint32_t addr = sBc + soff(rowB_c + h * 16, kb + kuB_c);
                LDSM4(b[h * 2][0], b[h * 2][1], b[h * 2 + 1][0], b[h * 2 + 1][1],
                      addr);
            }
            uint32_t a0, a1, a2, a3;
            LDSM4(a0, a1, a2, a3, sA + soff(rowA, kb + kuA_c));
#pragma unroll
            for (int ni = 0; ni < 4; ni++)
                MMA16816(acc[ni], a0, a1, a2, a3, b[ni][0], b[ni][1]);
        }

        // ---- phase A: per-row tile max -> smem rowmax ----------------------
        float m0 = -3.4e38f, m1 = -3.4e38f;
#pragma unroll
        for (int ni = 0; ni < 4; ni++) {
            m0 = fmaxf(m0, fmaxf(acc[ni][0], acc[ni][1]));
            m1 = fmaxf(m1, fmaxf(acc[ni][2], acc[ni][3]));
        }
        m0 = fmaxf(m0, __shfl_xor_sync(0xffffffffu, m0, 1));
        m0 = fmaxf(m0, __shfl_xor_sync(0xffffffffu, m0, 2));
        m1 = fmaxf(m1, __shfl_xor_sync(0xffffffffu, m1, 1));
        m1 = fmaxf(m1, __shfl_xor_sync(0xffffffffu, m1, 2));
        if ((lane & 3) == 0) {
            atomicMax(&rowmax_s[r0], ford(m0));
            atomicMax(&rowmax_s[r1], ford(m1));
        }
        if (t < NN / CT - 1) CPA_WAIT0();
        __syncthreads();   // rowmax visible to all; B prefetch landed

        // ---- phase B: append candidates above (rowmax - margin) ------------
        int ncol = t * CT + wn * 32 + cpair;
        float thr0 = unford(rowmax_s[r0]) - marg_s[r0];
        float thr1 = unford(rowmax_s[r1]) - marg_s[r1];
        if (m0 > thr0) {
#pragma unroll
            for (int ni = 0; ni < 4; ni++) {
                if (acc[ni][0] > thr0) {
                    int p = atomicAdd(&cnt_s[r0], 1);
                    if (p < RCAP) list_s[r0 * RCAP + p] = ncol + ni * 8;
                }
                if (acc[ni][1] > thr0) {
                    int p = atomicAdd(&cnt_s[r0], 1);
                    if (p < RCAP) list_s[r0 * RCAP + p] = ncol + ni * 8 + 1;
                }
            }
        }
        if (m1 > thr1) {
#pragma unroll
            for (int ni = 0; ni < 4; ni++) {
                if (acc[ni][2] > thr1) {
                    int p = atomicAdd(&cnt_s[r1], 1);
                    if (p < RCAP) list_s[r1 * RCAP + p] = ncol + ni * 8;
                }
                if (acc[ni][3] > thr1) {
                    int p = atomicAdd(&cnt_s[r1], 1);
                    if (p < RCAP) list_s[r1 * RCAP + p] = ncol + ni * 8 + 1;
                }
            }
        }
    }
    __syncthreads();   // lists complete

    // ---- tail 1: exact fp32 rescore (one warp per row, 8 rows/warp) --------
    for (int rr = wid; rr < RT; rr += 8) {
        int row = rb + rr;
        const float4* xp = (const float4*)(x + (size_t)row * DD);
        float4 xa = xp[lane * 2], xb2 = xp[lane * 2 + 1];
        float bestv = -3.4e38f;
        int bestn = 0;
        int c = cnt_s[rr];
        if (c <= RCAP) {
            for (int i = 0; i < c; i++) {
                int n = list_s[rr * RCAP + i];
                const float4* ep = (const float4*)(g_ehat + (size_t)n * DD);
                float4 e0 = ep[lane * 2], e1 = ep[lane * 2 + 1];
                float p = xa.x * e0.x + xa.y * e0.y + xa.z * e0.z + xa.w * e0.w +
                          xb2.x * e1.x + xb2.y * e1.y + xb2.z * e1.z +
                          xb2.w * e1.w;
#pragma unroll
                for (int o = 16; o > 0; o >>= 1)
                    p += __shfl_xor_sync(0xffffffffu, p, o);
                if (p > bestv || (p == bestv && n < bestn)) { bestv = p; bestn = n; }
            }
        } else {
            // overflow fallback (provably correct, ~never taken): full scan
            for (int n = 0; n < NN; n++) {
                const float4* ep = (const float4*)(g_ehat + (size_t)n * DD);
                float4 e0 = ep[lane * 2], e1 = ep[lane * 2 + 1];
                float p = xa.x * e0.x + xa.y * e0.y + xa.z * e0.z + xa.w * e0.w +
                          xb2.x * e1.x + xb2.y * e1.y + xb2.z * e1.z +
                          xb2.w * e1.w;
#pragma unroll
                for (int o = 16; o > 0; o >>= 1)
                    p += __shfl_xor_sync(0xffffffffu, p, o);
                if (p > bestv || (p == bestv && n < bestn)) { bestv = p; bestn = n; }
            }
        }
        if (lane == 0) bestn_s[rr] = bestn;
    }
    __syncthreads();

    // ---- tail 2: projection / x_q / commit epilogue (warp per row) ---------
    for (int rr = wid; rr < RT; rr += 8) {
        int row = rb + rr;
        int idx = bestn_s[rr];
        const float4* xp = (const float4*)(x + (size_t)row * DD);
        const float4* ep = (const float4*)(e + (size_t)idx * DD);
        float4 xa = xp[lane * 2], xb2 = xp[lane * 2 + 1];
        float4 ea = ep[lane * 2], eb2 = ep[lane * 2 + 1];
        float s1 = xa.x * ea.x + xa.y * ea.y + xa.z * ea.z + xa.w * ea.w +
                   xb2.x * eb2.x + xb2.y * eb2.y + xb2.z * eb2.z + xb2.w * eb2.w;
        float s2 = ea.x * ea.x + ea.y * ea.y + ea.z * ea.z + ea.w * ea.w +
                   eb2.x * eb2.x + eb2.y * eb2.y + eb2.z * eb2.z + eb2.w * eb2.w;
        float s3 = xa.x * xa.x + xa.y * xa.y + xa.z * xa.z + xa.w * xa.w +
                   xb2.x * xb2.x + xb2.y * xb2.y + xb2.z * xb2.z + xb2.w * xb2.w;
#pragma unroll
        for (int o = 16; o > 0; o >>= 1) {
            s1 += __shfl_xor_sync(0xffffffffu, s1, o);
            s2 += __shfl_xor_sync(0xffffffffu, s2, o);
            s3 += __shfl_xor_sync(0xffffffffu, s3, o);
        }
        float dot = s1, csq = s2, xsq = s3;
        float scalar = dot / (csq + 1e-8f);
        float4 o0, o1;
        o0.x = xa.x + (scalar * ea.x - xa.x);
        o0.y = xa.y + (scalar * ea.y - xa.y);
        o0.z = xa.z + (scalar * ea.z - xa.z);
        o0.w = xa.w + (scalar * ea.w - xa.w);
        o1.x = xb2.x + (scalar * eb2.x - xb2.x);
        o1.y = xb2.y + (scalar * eb2.y - xb2.y);
        o1.z = xb2.z + (scalar * eb2.z - xb2.z);
        o1.w = xb2.w + (scalar * eb2.w - xb2.w);
        float4* op = (float4*)(out + (size_t)row * DD);
        op[lane * 2] = o0;
        op[lane * 2 + 1] = o1;
        if (lane == 0) {
            float pn = fabsf(scalar) * sqrtf(csq);
            float commit = (scalar * dot) /
                           (fmaxf(pn, 1e-8f) * fmaxf(sqrtf(xsq), 1e-8f));
            g_commit[row] = 1.0f - commit;
            out[(size_t)BB * DD + 1 + row] = (float)idx;
            out[(size_t)BB * DD + 1 + BB + row] = scalar;
        }
    }
}

// ---------------- loss: deterministic 2-stage reduction --------------------
__global__ void loss_part_kernel() {
    __shared__ float sh[128];
    int b = blockIdx.x, t = threadIdx.x;
    sh[t] = g_commit[b * 128 + t];
    __syncthreads();
    for (int o = 64; o > 0; o >>= 1) {
        if (t < o) sh[t] += sh[t + o];
        __syncthreads();
    }
    if (t == 0) g_part[b] = sh[0];
}
__global__ void loss_fin_kernel(float* __restrict__ out) {
    __shared__ float sh[256];
    int t = threadIdx.x;
    sh[t] = g_part[t];
    __syncthreads();
    for (int o = 128; o > 0; o >>= 1) {
        if (t < o) sh[t] += sh[t + o];
        __syncthreads();
    }
    if (t == 0) out[(size_t)BB * DD] = 0.25f * sh[0] / (float)BB;
}

// ---------------------------------------------------------------------------
extern "C" void kernel_launch(void* const* d_in, const int* in_sizes, int n_in,
                              void* d_out, int out_size) {
    const float* x = (const float*)d_in[0];
    const float* e = (const float*)d_in[1];
    float* out = (float*)d_out;

    cudaFuncSetAttribute(gemm_kernel,
                         cudaFuncAttributeMaxDynamicSharedMemorySize, DYN_SMEM);
    prep_e_kernel<<<NN / 8, 256>>>(e);
    gemm_kernel<<<BB / RT, 256, DYN_SMEM>>>(x, e, out);
    loss_part_kernel<<<256, 128>>>();
    loss_fin_kernel<<<1, 256>>>(out);
}